// round 1
// baseline (speedup 1.0000x reference)
#include <cuda_runtime.h>

// CollisionLoss: pos [B=65536, N=24, 3] f32 -> scalar f32.
// For each batch: over masked pairs (i<j, i>=1, skip (2,3)),
//   sq = |p_i - p_j|^2 ; if sq < 0.25: sum += exp(-4*sq); cnt++
// out = (cnt>0 ? sum/cnt : 0) + 1e-6
// Trick: scale coords by s = sqrt(4*log2(e)) so term = 2^(-sq') (raw EX2),
// and collision test becomes sq' < 1.44269504.

#define THREADS 128
#define PTS 24
#define FLOATS_PER (PTS * 3)   // 72
#define SMEM_STRIDE 73         // 73 mod 32 = 9, coprime with 32 -> conflict-free
#define MAX_BLOCKS 1024

__device__ float g_partial_sum[MAX_BLOCKS];
__device__ float g_partial_cnt[MAX_BLOCKS];

__global__ __launch_bounds__(THREADS)
void collision_main_kernel(const float* __restrict__ pos, int B) {
    __shared__ float sm[THREADS * SMEM_STRIDE];
    __shared__ float wsum[THREADS / 32];
    __shared__ int   wcnt[THREADS / 32];

    const int tid   = threadIdx.x;
    const int bbase = blockIdx.x * THREADS;
    const int valid = min(THREADS, B - bbase);

    // ---- Stage: coalesced float4 loads gmem -> padded smem ----
    // valid*72 floats; 72 % 4 == 0 so float4 chunks never cross a batch row.
    {
        const float4* src4 = reinterpret_cast<const float4*>(pos + (size_t)bbase * FLOATS_PER);
        const int n4 = (valid * FLOATS_PER) >> 2;   // float4 count
        for (int q = tid; q < n4; q += THREADS) {
            float4 v = src4[q];
            int g = q << 2;                 // float index
            int b = g / FLOATS_PER;         // batch within block
            int w = g - b * FLOATS_PER;     // offset within batch (multiple of 4)
            float* d = &sm[b * SMEM_STRIDE + w];
            d[0] = v.x; d[1] = v.y; d[2] = v.z; d[3] = v.w;
        }
    }
    __syncthreads();

    // ---- Per-thread pair loop ----
    float lsum = 0.0f;
    int   lcnt = 0;
    if (tid < valid) {
        const float SCALE = 2.4022448929611436f;   // sqrt(4 * log2(e))
        float px[PTS], py[PTS], pz[PTS];
        const float* row = &sm[tid * SMEM_STRIDE];
        #pragma unroll
        for (int i = 1; i < PTS; i++) {            // point 0 excluded entirely
            px[i] = row[i * 3 + 0] * SCALE;
            py[i] = row[i * 3 + 1] * SCALE;
            pz[i] = row[i * 3 + 2] * SCALE;
        }
        #pragma unroll
        for (int i = 1; i < PTS; i++) {
            #pragma unroll
            for (int j = i + 1; j < PTS; j++) {
                if (i == 2 && j == 3) continue;    // excluded pair (compile-time elided)
                float dx = px[i] - px[j];
                float dy = py[i] - py[j];
                float dz = pz[i] - pz[j];
                float nsq = -dx * dx;
                nsq = fmaf(dy, -dy, nsq);
                nsq = fmaf(dz, -dz, nsq);          // nsq = -scaled_sq
                float e;
                asm("ex2.approx.f32 %0, %1;" : "=f"(e) : "f"(nsq));
                if (nsq > -1.44269504f) {          // sq < 0.25 in original units
                    lsum += e;
                    lcnt += 1;
                }
            }
        }
    }

    // ---- Reduce: warp shuffle, then cross-warp via smem ----
    #pragma unroll
    for (int o = 16; o > 0; o >>= 1) {
        lsum += __shfl_down_sync(0xffffffffu, lsum, o);
        lcnt += __shfl_down_sync(0xffffffffu, lcnt, o);
    }
    const int wid = tid >> 5, lid = tid & 31;
    if (lid == 0) { wsum[wid] = lsum; wcnt[wid] = lcnt; }
    __syncthreads();
    if (tid == 0) {
        float s = 0.0f; int c = 0;
        #pragma unroll
        for (int w = 0; w < THREADS / 32; w++) { s += wsum[w]; c += wcnt[w]; }
        g_partial_sum[blockIdx.x] = s;
        g_partial_cnt[blockIdx.x] = (float)c;
    }
}

__global__ __launch_bounds__(512)
void collision_final_kernel(float* __restrict__ out, int nblocks) {
    __shared__ float ssum[16];
    __shared__ float scnt[16];
    const int tid = threadIdx.x;
    float s = 0.0f, c = 0.0f;
    for (int i = tid; i < nblocks; i += 512) {
        s += g_partial_sum[i];
        c += g_partial_cnt[i];
    }
    #pragma unroll
    for (int o = 16; o > 0; o >>= 1) {
        s += __shfl_down_sync(0xffffffffu, s, o);
        c += __shfl_down_sync(0xffffffffu, c, o);
    }
    const int wid = tid >> 5, lid = tid & 31;
    if (lid == 0) { ssum[wid] = s; scnt[wid] = c; }
    __syncthreads();
    if (tid == 0) {
        float ts = 0.0f, tc = 0.0f;
        #pragma unroll
        for (int w = 0; w < 16; w++) { ts += ssum[w]; tc += scnt[w]; }
        float total = (tc > 0.0f) ? (ts / fmaxf(tc, 1.0f)) : 0.0f;
        out[0] = total + 1e-6f;
    }
}

extern "C" void kernel_launch(void* const* d_in, const int* in_sizes, int n_in,
                              void* d_out, int out_size) {
    const float* pos = (const float*)d_in[0];
    const int total_elems = in_sizes[0];
    const int B = total_elems / FLOATS_PER;
    int nblocks = (B + THREADS - 1) / THREADS;
    if (nblocks > MAX_BLOCKS) nblocks = MAX_BLOCKS;  // B=65536 -> 512 blocks

    collision_main_kernel<<<nblocks, THREADS>>>(pos, B);
    collision_final_kernel<<<1, 512>>>((float*)d_out, nblocks);
}

// round 2
// speedup vs baseline: 1.0271x; 1.0271x over previous
#include <cuda_runtime.h>

// CollisionLoss fused single-kernel version.
// pos [B=65536, N=24, 3] f32 -> scalar f32.
// Per batch, over masked pairs (i<j, i>=1, skip (2,3)):
//   sq = |p_i - p_j|^2 ; if sq < 0.25: sum += exp(-4*sq); cnt++
// out = (cnt>0 ? sum/cnt : 0) + 1e-6
// Coords pre-scaled by s = sqrt(4*log2(e)) so the term is 2^(-sq') (raw EX2)
// and the collision test is sq' < 1.44269504.
// Finalize is fused via the last-block-done pattern (no second launch).

#define THREADS 128
#define PTS 24
#define FLOATS_PER (PTS * 3)   // 72
#define SMEM_STRIDE 73         // 73 mod 32 = 9, coprime with 32 -> conflict-free
#define MAX_BLOCKS 1024

__device__ float g_psum[MAX_BLOCKS];
__device__ float g_pcnt[MAX_BLOCKS];
__device__ unsigned int g_ticket = 0;   // reset by the last block every launch

__global__ __launch_bounds__(THREADS)
void collision_fused_kernel(const float* __restrict__ pos, float* __restrict__ out, int B) {
    __shared__ float sm[THREADS * SMEM_STRIDE];
    __shared__ float wsum[THREADS / 32];
    __shared__ int   wcnt[THREADS / 32];
    __shared__ bool  amLast;

    const int tid   = threadIdx.x;
    const int bbase = blockIdx.x * THREADS;
    const int valid = min(THREADS, B - bbase);

    // ---- Stage: coalesced float4 loads gmem -> padded smem ----
    {
        const float4* src4 = reinterpret_cast<const float4*>(pos + (size_t)bbase * FLOATS_PER);
        const int n4 = (valid * FLOATS_PER) >> 2;
        for (int q = tid; q < n4; q += THREADS) {
            float4 v = src4[q];
            int g = q << 2;
            int b = g / FLOATS_PER;
            int w = g - b * FLOATS_PER;
            float* d = &sm[b * SMEM_STRIDE + w];
            d[0] = v.x; d[1] = v.y; d[2] = v.z; d[3] = v.w;
        }
    }
    __syncthreads();

    // ---- Per-thread pair loop (fully unrolled, coords in registers) ----
    float lsum = 0.0f;
    int   lcnt = 0;
    if (tid < valid) {
        const float SCALE = 2.4022448929611436f;   // sqrt(4 * log2(e))
        float px[PTS], py[PTS], pz[PTS];
        const float* row = &sm[tid * SMEM_STRIDE];
        #pragma unroll
        for (int i = 1; i < PTS; i++) {            // point 0 fully excluded
            px[i] = row[i * 3 + 0] * SCALE;
            py[i] = row[i * 3 + 1] * SCALE;
            pz[i] = row[i * 3 + 2] * SCALE;
        }
        #pragma unroll
        for (int i = 1; i < PTS; i++) {
            #pragma unroll
            for (int j = i + 1; j < PTS; j++) {
                if (i == 2 && j == 3) continue;    // excluded pair, elided at compile time
                float dx = px[i] - px[j];
                float dy = py[i] - py[j];
                float dz = pz[i] - pz[j];
                float nsq = -dx * dx;
                nsq = fmaf(dy, -dy, nsq);
                nsq = fmaf(dz, -dz, nsq);          // nsq = -scaled_sq
                float e;
                asm("ex2.approx.f32 %0, %1;" : "=f"(e) : "f"(nsq));
                if (nsq > -1.44269504f) {          // sq < 0.25 in original units
                    lsum += e;
                    lcnt += 1;
                }
            }
        }
    }

    // ---- Block reduce ----
    #pragma unroll
    for (int o = 16; o > 0; o >>= 1) {
        lsum += __shfl_down_sync(0xffffffffu, lsum, o);
        lcnt += __shfl_down_sync(0xffffffffu, lcnt, o);
    }
    const int wid = tid >> 5, lid = tid & 31;
    if (lid == 0) { wsum[wid] = lsum; wcnt[wid] = lcnt; }
    __syncthreads();
    if (tid == 0) {
        float s = 0.0f; int c = 0;
        #pragma unroll
        for (int w = 0; w < THREADS / 32; w++) { s += wsum[w]; c += wcnt[w]; }
        g_psum[blockIdx.x] = s;
        g_pcnt[blockIdx.x] = (float)c;
        __threadfence();
        unsigned int t = atomicAdd(&g_ticket, 1u);
        amLast = (t == gridDim.x - 1);
    }
    __syncthreads();

    // ---- Last block finalizes ----
    if (amLast) {
        const int nb = gridDim.x;
        float s = 0.0f, c = 0.0f;
        for (int i = tid; i < nb; i += THREADS) {
            s += g_psum[i];
            c += g_pcnt[i];
        }
        #pragma unroll
        for (int o = 16; o > 0; o >>= 1) {
            s += __shfl_down_sync(0xffffffffu, s, o);
            c += __shfl_down_sync(0xffffffffu, c, o);
        }
        if (lid == 0) { wsum[wid] = s; wcnt[wid] = __float_as_int(c); }
        __syncthreads();
        if (tid == 0) {
            float ts = 0.0f, tc = 0.0f;
            #pragma unroll
            for (int w = 0; w < THREADS / 32; w++) {
                ts += wsum[w];
                tc += __int_as_float(wcnt[w]);
            }
            float total = (tc > 0.0f) ? (ts / fmaxf(tc, 1.0f)) : 0.0f;
            out[0] = total + 1e-6f;
            g_ticket = 0;   // reset for the next graph replay
        }
    }
}

extern "C" void kernel_launch(void* const* d_in, const int* in_sizes, int n_in,
                              void* d_out, int out_size) {
    const float* pos = (const float*)d_in[0];
    const int B = in_sizes[0] / FLOATS_PER;
    int nblocks = (B + THREADS - 1) / THREADS;   // 512 for B=65536
    if (nblocks > MAX_BLOCKS) nblocks = MAX_BLOCKS;
    collision_fused_kernel<<<nblocks, THREADS>>>(pos, (float*)d_out, B);
}